// round 16
// baseline (speedup 1.0000x reference)
#include <cuda_runtime.h>
#include <cstdint>

#define BB 16
#define NND 512
#define EE 4
#define HH 64
#define EN 2048
#define A2 4096
#define AD 32
#define STEPS 5
#define GRIDN 256

// ------------- device scratch (no allocations) -------------
__device__ float g_hs  [BB*NND*HH];
__device__ float g_inc [BB*EN*HH];
__device__ float g_outg[BB*EN*HH];
__device__ float g_pain [4][(size_t)BB*NND*HH];   // bmm window partials
__device__ float g_paout[4][(size_t)BB*NND*HH];
__device__ float g_att [(size_t)BB*NND*128];
__device__ unsigned g_cnt = 0;
__device__ unsigned g_gen = 0;

// ------------- helpers -------------
__device__ __forceinline__ uint32_t tf(float x){
    uint32_t u; asm("cvt.rna.tf32.f32 %0, %1;" : "=r"(u) : "f"(x));
    return u;
}
__device__ __forceinline__ void tfsplit(float x, uint32_t& hi, uint32_t& lo){
    uint32_t h = tf(x);
    hi = h;
    lo = tf(x - __uint_as_float(h));
}
__device__ __forceinline__ void mma8(float* c, const uint32_t* a, const uint32_t* b){
    asm volatile("mma.sync.aligned.m16n8k8.row.col.f32.tf32.tf32.f32 "
        "{%0,%1,%2,%3}, {%4,%5,%6,%7}, {%8,%9}, {%0,%1,%2,%3};\n"
        : "+f"(c[0]), "+f"(c[1]), "+f"(c[2]), "+f"(c[3])
        : "r"(a[0]), "r"(a[1]), "r"(a[2]), "r"(a[3]), "r"(b[0]), "r"(b[1]));
}
__device__ __forceinline__ float sgm(float x){ return 1.0f/(1.0f + expf(-x)); }
__device__ __forceinline__ uint32_t smem_u32(const void* p){
    uint32_t a;
    asm("{ .reg .u64 t; cvta.to.shared.u64 t, %1; cvt.u32.u64 %0, t; }" : "=r"(a) : "l"(p));
    return a;
}

// grid barrier: proven R13 arrive/release; spin via volatile read + nanosleep
__device__ __forceinline__ void grid_sync(){
    __threadfence();
    __syncthreads();
    if (threadIdx.x == 0){
        unsigned gen = *(volatile unsigned*)&g_gen;
        if (atomicAdd(&g_cnt, 1u) == GRIDN - 1u){
            atomicExch(&g_cnt, 0u);
            __threadfence();
            atomicExch(&g_gen, gen + 1u);
        } else {
            while (*(volatile unsigned*)&g_gen == gen) __nanosleep(64);
        }
    }
    __syncthreads();
}

// ---- tf32x3 mma with in-register split; raw fp32 smem operands ----
template<int LDA, int LDB, int KS, int NI>
__device__ __forceinline__ void mma_frag(
    const float* sA, const float* sB,
    int mrow, int ncol, int gid, int q,
    float accM[2][NI][4], float accC[2][NI][4])
{
    #pragma unroll
    for (int ks = 0; ks < KS; ks++){
        const int k0 = ks*8;
        uint32_t ah[2][4], al[2][4];
        #pragma unroll
        for (int mi = 0; mi < 2; mi++){
            const int r = mrow + mi*16 + gid;
            tfsplit(sA[r*LDA+k0+q],       ah[mi][0], al[mi][0]);
            tfsplit(sA[(r+8)*LDA+k0+q],   ah[mi][1], al[mi][1]);
            tfsplit(sA[r*LDA+k0+q+4],     ah[mi][2], al[mi][2]);
            tfsplit(sA[(r+8)*LDA+k0+q+4], ah[mi][3], al[mi][3]);
        }
        #pragma unroll
        for (int ni = 0; ni < NI; ni++){
            const int c = ncol + ni*8 + gid;
            uint32_t bh[2], bl[2];
            tfsplit(sB[(k0+q)*LDB+c],   bh[0], bl[0]);
            tfsplit(sB[(k0+q+4)*LDB+c], bh[1], bl[1]);
            #pragma unroll
            for (int mi = 0; mi < 2; mi++){
                mma8(accM[mi][ni], ah[mi], bh);
                mma8(accC[mi][ni], al[mi], bh);
                mma8(accC[mi][ni], ah[mi], bl);
            }
        }
    }
}

// =====================================================================
// phase: proj — 256 tiles, one per CTA. raw smem A[128][68] + W1,W2[64][72]
// 256 thr, 8 warps 4m x 2n (warp tile 32x32). Split-at-load (bit-identical).
// =====================================================================
__device__ __noinline__ void proj_phase(
    const float* __restrict__ inw, const float* __restrict__ inb,
    const float* __restrict__ outw, const float* __restrict__ outb, float* sm)
{
    float* sA  = sm;             // 128*68
    float* sW1 = sA + 128*68;    // 64*72
    float* sW2 = sW1 + 64*72;
    const int x = blockIdx.x;
    const int mt = x & 3, e = (x>>2)&3, b = x>>4;
    const int t = threadIdx.x;
    const float* hsP = g_hs + ((size_t)b*NND + mt*128)*HH;

    #pragma unroll
    for (int j = 0; j < 8; j++){
        int idx = t + j*256, r = idx>>4, c = (idx&15)*4;
        *reinterpret_cast<float4*>(sA + r*68 + c) =
            *reinterpret_cast<const float4*>(hsP + (size_t)r*HH + c);
    }
    const float* wi = inw + (size_t)e*4096;
    const float* wo = outw + (size_t)e*4096;
    #pragma unroll
    for (int j = 0; j < 4; j++){
        int idx = t + j*256, r = idx>>4, c = (idx&15)*4;
        *reinterpret_cast<float4*>(sW1 + r*72 + c) = *reinterpret_cast<const float4*>(wi + (size_t)r*64 + c);
        *reinterpret_cast<float4*>(sW2 + r*72 + c) = *reinterpret_cast<const float4*>(wo + (size_t)r*64 + c);
    }
    __syncthreads();

    const int warp = t>>5, lane = t&31, gid = lane>>2, q = lane&3;
    const int mrow = (warp>>1)*32, ncol = (warp&1)*32;
    const size_t mBase = (size_t)b*EN + (size_t)e*NND + (size_t)mt*128;
    {
        float aM[2][4][4] = {}, aC[2][4][4] = {};
        mma_frag<68,72,8,4>(sA, sW1, mrow, ncol, gid, q, aM, aC);
        #pragma unroll
        for (int mi = 0; mi < 2; mi++)
        #pragma unroll
        for (int ni = 0; ni < 4; ni++)
        #pragma unroll
        for (int e2 = 0; e2 < 4; e2++){
            const int fr = mrow + mi*16 + gid + ((e2&2)?8:0);
            const int fc = ncol + ni*8 + q*2 + (e2&1);
            g_inc[(mBase+fr)*HH + fc] = (aM[mi][ni][e2] + aC[mi][ni][e2]) + __ldg(inb + e*64 + fc);
        }
    }
    {
        float aM[2][4][4] = {}, aC[2][4][4] = {};
        mma_frag<68,72,8,4>(sA, sW2, mrow, ncol, gid, q, aM, aC);
        #pragma unroll
        for (int mi = 0; mi < 2; mi++)
        #pragma unroll
        for (int ni = 0; ni < 4; ni++)
        #pragma unroll
        for (int e2 = 0; e2 < 4; e2++){
            const int fr = mrow + mi*16 + gid + ((e2&2)?8:0);
            const int fc = ncol + ni*8 + q*2 + (e2&1);
            g_outg[(mBase+fr)*HH + fc] = (aM[mi][ni][e2] + aC[mi][ni][e2]) + __ldg(outb + e*64 + fc);
        }
    }
}

// =====================================================================
// phase: bmm — K-split x2, 256 tiles (= grid). 3-stage cp.async ring.
// Window (512-K) float partials to g_pain/g_paout. (R15 body, 1-D decode)
// =====================================================================
#define BMM_STG 6912
__device__ __forceinline__ void bmm_issue_chunk(
    const float* Ag, const float* Bg, uint32_t sA_u32, uint32_t sB_u32,
    int kk, int t)
{
    #pragma unroll
    for (int j = 0; j < 4; j++){                 // A: 1024 x 16B granules
        int g = t + j*256, r = g>>3, c4 = (g&7)*4;
        uint32_t dst = sA_u32 + (uint32_t)(r*36 + c4)*4;
        const float* src = Ag + (size_t)r*A2 + kk + c4;
        asm volatile("cp.async.cg.shared.global [%0], [%1], 16;" :: "r"(dst), "l"(src));
    }
    #pragma unroll
    for (int j = 0; j < 2; j++){                 // B: 512 x 16B granules
        int g = t + j*256, r = g>>4, c4 = (g&15)*4;
        uint32_t dst = sB_u32 + (uint32_t)(r*72 + c4)*4;
        const float* src = Bg + (size_t)(kk + r)*HH + c4;
        asm volatile("cp.async.cg.shared.global [%0], [%1], 16;" :: "r"(dst), "l"(src));
    }
    asm volatile("cp.async.commit_group;" ::: "memory");
}

__device__ __noinline__ void bmm_phase(const float* __restrict__ Abig, float* sm){
    const int x = blockIdx.x;
    const int mt = x & 3, y = x >> 2;
    const int ks = y & 1, half = (y>>1) & 1, b = y >> 2;
    const int t = threadIdx.x;
    const int kbase = ks * 1024;
    const float* Ag = Abig + ((size_t)b*NND + mt*128)*A2 + (size_t)half*EN + kbase;
    const float* Bg = (half ? g_outg : g_inc) + (size_t)b*EN*HH + (size_t)kbase*HH;
    const size_t outBase = ((size_t)b*NND + mt*128)*HH;
    const uint32_t sbase = smem_u32(sm);

    bmm_issue_chunk(Ag, Bg, sbase, sbase + 4608u*4, 0, t);
    bmm_issue_chunk(Ag, Bg, sbase + (uint32_t)BMM_STG*4, sbase + (uint32_t)(BMM_STG+4608)*4, 32, t);

    const int warp = t>>5, lane = t&31, gid = lane>>2, q = lane&3;
    const int mrow = (warp>>1)*32, ncol = (warp&1)*32;     // 4m x 2n
    float accM[2][4][4] = {}, accC[2][4][4] = {};

    for (int it = 0; it < 32; it++){
        if (it + 2 < 32){
            const int stg = (it+2) % 3;
            const uint32_t sb = sbase + (uint32_t)(stg*BMM_STG)*4;
            bmm_issue_chunk(Ag, Bg, sb, sb + 4608u*4, (it+2)*32, t);
        }
        if (it < 30)       asm volatile("cp.async.wait_group 2;" ::: "memory");
        else if (it == 30) asm volatile("cp.async.wait_group 1;" ::: "memory");
        else               asm volatile("cp.async.wait_group 0;" ::: "memory");
        __syncthreads();
        const float* base = sm + (it % 3)*BMM_STG;
        mma_frag<36,72,4,4>(base, base + 4608, mrow, ncol, gid, q, accM, accC);
        if ((it & 15) == 15){
            float* P = (half ? g_paout : g_pain)[ks*2 + (it>>4)];
            #pragma unroll
            for (int mi = 0; mi < 2; mi++)
            #pragma unroll
            for (int ni = 0; ni < 4; ni++)
            #pragma unroll
            for (int e2 = 0; e2 < 4; e2++){
                const int fr = mrow + mi*16 + gid + ((e2&2)?8:0);
                const int fc = ncol + ni*8 + q*2 + (e2&1);
                P[outBase + (size_t)fr*HH + fc] = accM[mi][ni][e2] + accC[mi][ni][e2];
                accM[mi][ni][e2] = 0.0f;
                accC[mi][ni][e2] = 0.0f;
            }
        }
        __syncthreads();
    }
}

// =====================================================================
// phase: gate — 128 tiles (CTAs 0..127). sG kept in REGISTERS (producer
// and consumer fragment maps coincide). smem: sA[64][196] + sW[32][72].
// =====================================================================
__device__ __noinline__ void gate_phase(
    const float* __restrict__ uw, const float* __restrict__ rw,
    const float* __restrict__ tw, const float* __restrict__ ub,
    const float* __restrict__ rb, const float* __restrict__ tb, float* sm)
{
    const int x = blockIdx.x;
    if (x >= 128) return;
    float* sA = sm;                  // 64*196
    float* sW = sA + 64*196;         // 32*72
    const int mt = x & 7, b = x >> 3, t = threadIdx.x;
    const size_t nodeBase = (size_t)b*NND + (size_t)mt*64;

    // assemble A panel: a_in (sum of 4 partials) | a_out (sum) | hs
    #pragma unroll
    for (int j = 0; j < 4; j++){
        int idx = t + j*256, r = idx>>4, c = (idx&15)*4;
        const size_t off = (nodeBase + r)*HH + c;
        float4 vi = *reinterpret_cast<const float4*>(&g_pain[0][off]);
        float4 vo = *reinterpret_cast<const float4*>(&g_paout[0][off]);
        #pragma unroll
        for (int w = 1; w < 4; w++){
            float4 pi = *reinterpret_cast<const float4*>(&g_pain[w][off]);
            float4 po = *reinterpret_cast<const float4*>(&g_paout[w][off]);
            vi.x += pi.x; vi.y += pi.y; vi.z += pi.z; vi.w += pi.w;
            vo.x += po.x; vo.y += po.y; vo.z += po.z; vo.w += po.w;
        }
        *reinterpret_cast<float4*>(sA + r*196 + c)       = vi;
        *reinterpret_cast<float4*>(sA + r*196 + 64 + c)  = vo;
        *reinterpret_cast<float4*>(sA + r*196 + 128 + c) =
            *reinterpret_cast<const float4*>(g_hs + off);
    }
    __syncthreads();

    const int warp = t>>5, lane = t&31, gid = lane>>2, q = lane&3;
    const int mrow = (warp>>2)*32, ncol = (warp&3)*16;

    float zf[16], rf[16], hf[16];
    #pragma unroll
    for (int nt = 0; nt < 3; nt++){
        const float* W    = (nt==0) ? uw : (nt==1) ? rw : tw;
        const float* bias = (nt==0) ? ub : (nt==1) ? rb : tb;
        const int kmax = (nt==2) ? 4 : 6;
        float accM[2][2][4] = {}, accC[2][2][4] = {};
        for (int kc = 0; kc < kmax; kc++){
            #pragma unroll
            for (int j = 0; j < 2; j++){
                int idx = t + j*256, r = idx>>4, c = (idx&15)*4;
                *reinterpret_cast<float4*>(sW + r*72 + c) =
                    *reinterpret_cast<const float4*>(W + (size_t)(kc*32+r)*64 + c);
            }
            __syncthreads();
            mma_frag<196,72,4,2>(sA + kc*32, sW, mrow, ncol, gid, q, accM, accC);
            __syncthreads();
        }
        #pragma unroll
        for (int mi = 0; mi < 2; mi++)
        #pragma unroll
        for (int ni = 0; ni < 2; ni++)
        #pragma unroll
        for (int e2 = 0; e2 < 4; e2++){
            const int fc = ncol + ni*8 + q*2 + (e2&1);
            const int fi = ((mi*2+ni)<<2) + e2;
            float v = (accM[mi][ni][e2] + accC[mi][ni][e2]) + __ldg(bias + fc);
            if (nt == 0) zf[fi] = v;
            else if (nt == 1) rf[fi] = v;
            else hf[fi] = v;
        }
    }

    // rh = sigmoid(r_pre) * hs -> sA cols 0..63 (fragment-owner writes)
    #pragma unroll
    for (int mi = 0; mi < 2; mi++)
    #pragma unroll
    for (int ni = 0; ni < 2; ni++)
    #pragma unroll
    for (int e2 = 0; e2 < 4; e2++){
        const int fr = mrow + mi*16 + gid + ((e2&2)?8:0);
        const int fc = ncol + ni*8 + q*2 + (e2&1);
        const int fi = ((mi*2+ni)<<2) + e2;
        sA[fr*196 + fc] = sA[fr*196 + 128 + fc] * sgm(rf[fi]);
    }
    __syncthreads();

    // stage 2: h_bot = rh @ tw[128:192]
    float acc2M[2][2][4] = {}, acc2C[2][2][4] = {};
    for (int kc = 0; kc < 2; kc++){
        #pragma unroll
        for (int j = 0; j < 2; j++){
            int idx = t + j*256, r = idx>>4, c = (idx&15)*4;
            *reinterpret_cast<float4*>(sW + r*72 + c) =
                *reinterpret_cast<const float4*>(tw + (size_t)(128 + kc*32 + r)*64 + c);
        }
        __syncthreads();
        mma_frag<196,72,4,2>(sA + kc*32, sW, mrow, ncol, gid, q, acc2M, acc2C);
        __syncthreads();
    }

    // epilogue: hs update
    #pragma unroll
    for (int mi = 0; mi < 2; mi++)
    #pragma unroll
    for (int ni = 0; ni < 2; ni++)
    #pragma unroll
    for (int e2 = 0; e2 < 4; e2++){
        const int fr = mrow + mi*16 + gid + ((e2&2)?8:0);
        const int fc = ncol + ni*8 + q*2 + (e2&1);
        const int fi = ((mi*2+ni)<<2) + e2;
        const size_t node = nodeBase + fr;
        float z  = sgm(zf[fi]);
        float h  = tanhf(hf[fi] + (acc2M[mi][ni][e2] + acc2C[mi][ni][e2]));
        float hv = sA[fr*196 + 128 + fc];
        g_hs[node*HH + fc] = (1.0f - z)*hv + z*h;
    }
}

// =====================================================================
// phase: att — 128 tiles (CTAs 0..127)
// =====================================================================
__device__ __noinline__ void att_phase(
    const float* __restrict__ ann, const float* __restrict__ aw,
    const float* __restrict__ ab, const float* __restrict__ sw,
    const float* __restrict__ sb, float* sm)
{
    const int x = blockIdx.x;
    if (x >= 128) return;
    float* sA = sm;           // 128*36
    float* sB = sA + 128*36;  // 32*72
    const int mt = x & 3, b = (x>>2)&15, nt = x>>6;
    const int t = threadIdx.x;
    const float* W    = nt ? sw : aw;
    const float* bias = nt ? sb : ab;
    const size_t nodeBase = (size_t)b*NND + (size_t)mt*128;
    const int warp = t>>5, lane = t&31, gid = lane>>2, q = lane&3;
    const int mrow = (warp>>1)*32, ncol = (warp&1)*32;
    float accM[2][4][4] = {}, accC[2][4][4] = {};
    for (int kc = 0; kc < 3; kc++){
        const int k0 = kc*32;
        const float* Ag; int rs;
        if (kc < 2){ Ag = g_hs + nodeBase*HH + k0; rs = HH; }
        else       { Ag = ann + nodeBase*AD;       rs = AD; }
        #pragma unroll
        for (int j = 0; j < 4; j++){
            int idx = t + j*256, r = idx>>3, c = (idx&7)*4;
            *reinterpret_cast<float4*>(sA + r*36 + c) =
                *reinterpret_cast<const float4*>(Ag + (size_t)r*rs + c);
        }
        #pragma unroll
        for (int j = 0; j < 2; j++){
            int idx = t + j*256, r = idx>>4, c = (idx&15)*4;
            *reinterpret_cast<float4*>(sB + r*72 + c) =
                *reinterpret_cast<const float4*>(W + (size_t)(k0+r)*64 + c);
        }
        __syncthreads();
        mma_frag<36,72,4,4>(sA, sB, mrow, ncol, gid, q, accM, accC);
        __syncthreads();
    }
    #pragma unroll
    for (int mi = 0; mi < 2; mi++)
    #pragma unroll
    for (int ni = 0; ni < 4; ni++)
    #pragma unroll
    for (int e2 = 0; e2 < 4; e2++){
        const int fr = mrow + mi*16 + gid + ((e2&2)?8:0);
        const int fc = ncol + ni*8 + q*2 + (e2&1);
        g_att[(nodeBase+fr)*128 + nt*64 + fc] =
            (accM[mi][ni][e2] + accC[mi][ni][e2]) + __ldg(bias + fc);
    }
}

// =====================================================================
// phase: reduce — CTAs 0..15, fp64
// =====================================================================
__device__ __noinline__ void reduce_phase(float* __restrict__ out, float* sm){
    if (blockIdx.x >= BB) return;
    double* red = reinterpret_cast<double*>(sm);
    const int b = blockIdx.x, t = threadIdx.x;
    const int c = t & 63, seg = t >> 6;
    double acc = 0.0;
    for (int n = seg; n < NND; n += 4){
        const float* p = g_att + ((size_t)b*NND + n)*128;
        double attn = 1.0/(1.0 + exp(-(double)p[c]));
        double ts   = tanh((double)p[64 + c]);
        acc += attn * ts;
    }
    red[t] = acc;
    __syncthreads();
    if (t < 64){
        double s = red[t] + red[t+64] + red[t+128] + red[t+192];
        out[(size_t)b*64 + t] = (float)tanh(s);
    }
}

// =====================================================================
// the one persistent kernel — 256 CTAs x 256 thr, 2 CTAs/SM
// =====================================================================
__global__ void __launch_bounds__(256, 2)
ggnn_fused(const float* __restrict__ ann, const float* __restrict__ Abig,
           const float* __restrict__ inw, const float* __restrict__ inb,
           const float* __restrict__ outw, const float* __restrict__ outb,
           const float* __restrict__ uw, const float* __restrict__ ub,
           const float* __restrict__ rw, const float* __restrict__ rb,
           const float* __restrict__ tw, const float* __restrict__ tb,
           const float* __restrict__ aw, const float* __restrict__ ab,
           const float* __restrict__ sw, const float* __restrict__ sb,
           float* __restrict__ out)
{
    extern __shared__ float sm[];
    for (int s = 0; s < STEPS; s++){
        proj_phase(inw, inb, outw, outb, sm);
        grid_sync();
        bmm_phase(Abig, sm);
        grid_sync();
        gate_phase(uw, rw, tw, ub, rb, tb, sm);
        grid_sync();
    }
    att_phase(ann, aw, ab, sw, sb, sm);
    grid_sync();
    reduce_phase(out, sm);
}

// =====================================================================
extern "C" void kernel_launch(void* const* d_in, const int* in_sizes, int n_in,
                              void* d_out, int out_size){
    const float* hs   = (const float*)d_in[0];
    const float* ann  = (const float*)d_in[1];
    const float* Abig = (const float*)d_in[2];
    const float* inw  = (const float*)d_in[3];
    const float* inb  = (const float*)d_in[4];
    const float* outw = (const float*)d_in[5];
    const float* outb = (const float*)d_in[6];
    const float* uw   = (const float*)d_in[7];
    const float* ub   = (const float*)d_in[8];
    const float* rw   = (const float*)d_in[9];
    const float* rb   = (const float*)d_in[10];
    const float* tw   = (const float*)d_in[11];
    const float* tb   = (const float*)d_in[12];
    const float* aw   = (const float*)d_in[13];
    const float* ab   = (const float*)d_in[14];
    const float* sw   = (const float*)d_in[15];
    const float* sb   = (const float*)d_in[16];

    const int SMEM = 3 * BMM_STG * 4;            // 82944 B = max phase need
    cudaFuncSetAttribute(ggnn_fused, cudaFuncAttributeMaxDynamicSharedMemorySize, SMEM);

    cudaMemcpyToSymbolAsync(g_hs, hs, sizeof(float)*BB*NND*HH, 0,
                            cudaMemcpyDeviceToDevice, 0);

    ggnn_fused<<<GRIDN, 256, SMEM>>>(ann, Abig, inw, inb, outw, outb,
                                     uw, ub, rw, rb, tw, tb,
                                     aw, ab, sw, sb, (float*)d_out);
}

// round 17
// speedup vs baseline: 1.0530x; 1.0530x over previous
#include <cuda_runtime.h>
#include <cstdint>

#define BB 16
#define NND 512
#define EE 4
#define HH 64
#define EN 2048
#define A2 4096
#define AD 32
#define STEPS 5

// ------------- device scratch (no allocations) -------------
__device__ float g_hs   [BB*NND*HH];
__device__ float g_inch [BB*EN*HH];     // proj outputs pre-split (tf32 hi/lo)
__device__ float g_incl [BB*EN*HH];
__device__ float g_outgh[BB*EN*HH];
__device__ float g_outgl[BB*EN*HH];
__device__ float g_pain [4][(size_t)BB*NND*HH];   // bmm window partials
__device__ float g_paout[4][(size_t)BB*NND*HH];
__device__ float g_att  [(size_t)BB*NND*128];
__device__ float g_wch  [192*192];      // [uw|rw|tw(pad0)] hi
__device__ float g_wcl  [192*192];      // lo
__device__ float g_bcat [192];          // [ub|rb|tb]

// ------------- helpers -------------
__device__ __forceinline__ uint32_t tf(float x){
    uint32_t u; asm("cvt.rna.tf32.f32 %0, %1;" : "=r"(u) : "f"(x));
    return u;
}
__device__ __forceinline__ uint32_t fu(float x){ return __float_as_uint(x); }
__device__ __forceinline__ void tfsplit(float x, uint32_t& hi, uint32_t& lo){
    uint32_t h = tf(x);
    hi = h;
    lo = tf(x - __uint_as_float(h));
}
__device__ __forceinline__ void st_split4(float* hb, float* lb, int off, float4 v){
    float4 h, l;
    h.x = __uint_as_float(tf(v.x)); l.x = __uint_as_float(tf(v.x - h.x));
    h.y = __uint_as_float(tf(v.y)); l.y = __uint_as_float(tf(v.y - h.y));
    h.z = __uint_as_float(tf(v.z)); l.z = __uint_as_float(tf(v.z - h.z));
    h.w = __uint_as_float(tf(v.w)); l.w = __uint_as_float(tf(v.w - h.w));
    *reinterpret_cast<float4*>(hb + off) = h;
    *reinterpret_cast<float4*>(lb + off) = l;
}
__device__ __forceinline__ void mma8(float* c, const uint32_t* a, const uint32_t* b){
    asm volatile("mma.sync.aligned.m16n8k8.row.col.f32.tf32.tf32.f32 "
        "{%0,%1,%2,%3}, {%4,%5,%6,%7}, {%8,%9}, {%0,%1,%2,%3};\n"
        : "+f"(c[0]), "+f"(c[1]), "+f"(c[2]), "+f"(c[3])
        : "r"(a[0]), "r"(a[1]), "r"(a[2]), "r"(a[3]), "r"(b[0]), "r"(b[1]));
}
__device__ __forceinline__ float sgm(float x){ return 1.0f/(1.0f + expf(-x)); }
__device__ __forceinline__ uint32_t smem_u32(const void* p){
    uint32_t a;
    asm("{ .reg .u64 t; cvta.to.shared.u64 t, %1; cvt.u32.u64 %0, t; }" : "=r"(a) : "l"(p));
    return a;
}

// ---- mma, both operands pre-split in smem (proj) ----
template<int LDA, int LDB, int KS, int NI>
__device__ __forceinline__ void mma_split(
    const float* sAh, const float* sAl, const float* sBh, const float* sBl,
    int mrow, int ncol, int gid, int q,
    float accM[2][NI][4], float accC[2][NI][4])
{
    #pragma unroll
    for (int ks = 0; ks < KS; ks++){
        const int k0 = ks*8;
        uint32_t ah[2][4], al[2][4];
        #pragma unroll
        for (int mi = 0; mi < 2; mi++){
            const int r = mrow + mi*16 + gid;
            ah[mi][0]=fu(sAh[r*LDA+k0+q]);       al[mi][0]=fu(sAl[r*LDA+k0+q]);
            ah[mi][1]=fu(sAh[(r+8)*LDA+k0+q]);   al[mi][1]=fu(sAl[(r+8)*LDA+k0+q]);
            ah[mi][2]=fu(sAh[r*LDA+k0+q+4]);     al[mi][2]=fu(sAl[r*LDA+k0+q+4]);
            ah[mi][3]=fu(sAh[(r+8)*LDA+k0+q+4]); al[mi][3]=fu(sAl[(r+8)*LDA+k0+q+4]);
        }
        #pragma unroll
        for (int ni = 0; ni < NI; ni++){
            const int c = ncol + ni*8 + gid;
            uint32_t bh[2], bl[2];
            bh[0]=fu(sBh[(k0+q)*LDB+c]);   bh[1]=fu(sBh[(k0+q+4)*LDB+c]);
            bl[0]=fu(sBl[(k0+q)*LDB+c]);   bl[1]=fu(sBl[(k0+q+4)*LDB+c]);
            #pragma unroll
            for (int mi = 0; mi < 2; mi++){
                mma8(accM[mi][ni], ah[mi], bh);
                mma8(accC[mi][ni], al[mi], bh);
                mma8(accC[mi][ni], ah[mi], bl);
            }
        }
    }
}
// ---- mma, A tfsplit in-register, B pre-split in smem ----
template<int LDA, int LDB, int KS, int NI>
__device__ __forceinline__ void mma_fragB(
    const float* sA, const float* sBh, const float* sBl,
    int mrow, int ncol, int gid, int q,
    float accM[2][NI][4], float accC[2][NI][4])
{
    #pragma unroll
    for (int ks = 0; ks < KS; ks++){
        const int k0 = ks*8;
        uint32_t ah[2][4], al[2][4];
        #pragma unroll
        for (int mi = 0; mi < 2; mi++){
            const int r = mrow + mi*16 + gid;
            tfsplit(sA[r*LDA+k0+q],       ah[mi][0], al[mi][0]);
            tfsplit(sA[(r+8)*LDA+k0+q],   ah[mi][1], al[mi][1]);
            tfsplit(sA[r*LDA+k0+q+4],     ah[mi][2], al[mi][2]);
            tfsplit(sA[(r+8)*LDA+k0+q+4], ah[mi][3], al[mi][3]);
        }
        #pragma unroll
        for (int ni = 0; ni < NI; ni++){
            const int c = ncol + ni*8 + gid;
            uint32_t bh[2], bl[2];
            bh[0]=fu(sBh[(k0+q)*LDB+c]);   bh[1]=fu(sBh[(k0+q+4)*LDB+c]);
            bl[0]=fu(sBl[(k0+q)*LDB+c]);   bl[1]=fu(sBl[(k0+q+4)*LDB+c]);
            #pragma unroll
            for (int mi = 0; mi < 2; mi++){
                mma8(accM[mi][ni], ah[mi], bh);
                mma8(accC[mi][ni], al[mi], bh);
                mma8(accC[mi][ni], ah[mi], bl);
            }
        }
    }
}
// ---- mma, both tfsplit in-register (att, gate stage-2) ----
template<int LDA, int LDB, int KS, int NI>
__device__ __forceinline__ void mma_frag(
    const float* sA, const float* sB,
    int mrow, int ncol, int gid, int q,
    float accM[2][NI][4], float accC[2][NI][4])
{
    #pragma unroll
    for (int ks = 0; ks < KS; ks++){
        const int k0 = ks*8;
        uint32_t ah[2][4], al[2][4];
        #pragma unroll
        for (int mi = 0; mi < 2; mi++){
            const int r = mrow + mi*16 + gid;
            tfsplit(sA[r*LDA+k0+q],       ah[mi][0], al[mi][0]);
            tfsplit(sA[(r+8)*LDA+k0+q],   ah[mi][1], al[mi][1]);
            tfsplit(sA[r*LDA+k0+q+4],     ah[mi][2], al[mi][2]);
            tfsplit(sA[(r+8)*LDA+k0+q+4], ah[mi][3], al[mi][3]);
        }
        #pragma unroll
        for (int ni = 0; ni < NI; ni++){
            const int c = ncol + ni*8 + gid;
            uint32_t bh[2], bl[2];
            tfsplit(sB[(k0+q)*LDB+c],   bh[0], bl[0]);
            tfsplit(sB[(k0+q+4)*LDB+c], bh[1], bl[1]);
            #pragma unroll
            for (int mi = 0; mi < 2; mi++){
                mma8(accM[mi][ni], ah[mi], bh);
                mma8(accC[mi][ni], al[mi], bh);
                mma8(accC[mi][ni], ah[mi], bl);
            }
        }
    }
}

// =====================================================================
// setup: build concatenated gate weight [uw|rw|tw(pad0)] pre-split + bias
// =====================================================================
__global__ void setup_kernel(const float* __restrict__ uw, const float* __restrict__ rw,
                             const float* __restrict__ tw, const float* __restrict__ ub,
                             const float* __restrict__ rb, const float* __restrict__ tb){
    int i = blockIdx.x*blockDim.x + threadIdx.x;
    if (i < 192*192){
        int k = i/192, j = i%192;
        float v = (j < 64)  ? uw[k*64 + j]
                : (j < 128) ? rw[k*64 + (j-64)]
                : (k < 128) ? tw[k*64 + (j-128)] : 0.0f;
        uint32_t h, l; tfsplit(v, h, l);
        g_wch[i] = __uint_as_float(h);
        g_wcl[i] = __uint_as_float(l);
    }
    if (i < 192)
        g_bcat[i] = (i < 64) ? ub[i] : (i < 128) ? rb[i-64] : tb[i-128];
}

// =====================================================================
// proj: grid (4mt, E, B), 512 thr. Outputs stored PRE-SPLIT (hi/lo).
// =====================================================================
__global__ void __launch_bounds__(512)
proj_kernel(const float* __restrict__ inw, const float* __restrict__ inb,
            const float* __restrict__ outw, const float* __restrict__ outb){
    extern __shared__ float sm[];
    float* sAh = sm;                 // 128*68
    float* sAl = sAh + 128*68;
    float* sWh = sAl + 128*68;       // 64*72
    float* sWl = sWh + 64*72;
    const int mt = blockIdx.x, e = blockIdx.y, b = blockIdx.z, t = threadIdx.x;
    const float* hsP = g_hs + ((size_t)b*NND + mt*128)*HH;

    #pragma unroll
    for (int j = 0; j < 4; j++){
        int idx = t + j*512, r = idx>>4, c = (idx&15)*4;
        st_split4(sAh, sAl, r*68 + c,
                  *reinterpret_cast<const float4*>(hsP + (size_t)r*HH + c));
    }
    const float* wi = inw + (size_t)e*4096;
    #pragma unroll
    for (int j = 0; j < 2; j++){
        int idx = t + j*512, r = idx>>4, c = (idx&15)*4;
        st_split4(sWh, sWl, r*72 + c,
                  *reinterpret_cast<const float4*>(wi + (size_t)r*64 + c));
    }
    __syncthreads();

    const int warp = t>>5, lane = t&31, gid = lane>>2, q = lane&3;
    const int mrow = (warp>>2)*32, ncol = (warp&3)*16;
    float aiM[2][2][4] = {}, aiC[2][2][4] = {};
    float aoM[2][2][4] = {}, aoC[2][2][4] = {};
    mma_split<68,72,8,2>(sAh, sAl, sWh, sWl, mrow, ncol, gid, q, aiM, aiC);
    __syncthreads();
    const float* wo = outw + (size_t)e*4096;
    #pragma unroll
    for (int j = 0; j < 2; j++){
        int idx = t + j*512, r = idx>>4, c = (idx&15)*4;
        st_split4(sWh, sWl, r*72 + c,
                  *reinterpret_cast<const float4*>(wo + (size_t)r*64 + c));
    }
    __syncthreads();
    mma_split<68,72,8,2>(sAh, sAl, sWh, sWl, mrow, ncol, gid, q, aoM, aoC);

    const size_t mBase = (size_t)b*EN + (size_t)e*NND + (size_t)mt*128;
    #pragma unroll
    for (int mi = 0; mi < 2; mi++)
    #pragma unroll
    for (int ni = 0; ni < 2; ni++)
    #pragma unroll
    for (int e2 = 0; e2 < 4; e2++){
        const int fr = mrow + mi*16 + gid + ((e2&2)?8:0);
        const int fc = ncol + ni*8 + q*2 + (e2&1);
        const size_t off = (mBase+fr)*HH + fc;
        float vi = (aiM[mi][ni][e2] + aiC[mi][ni][e2]) + __ldg(inb + e*64 + fc);
        float vo = (aoM[mi][ni][e2] + aoC[mi][ni][e2]) + __ldg(outb + e*64 + fc);
        uint32_t h, l;
        tfsplit(vi, h, l);
        g_inch[off] = __uint_as_float(h);  g_incl[off] = __uint_as_float(l);
        tfsplit(vo, h, l);
        g_outgh[off] = __uint_as_float(h); g_outgl[off] = __uint_as_float(l);
    }
}

// =====================================================================
// bmm: K-split x2. grid (4mt, 64), 256 thr, 2 CTAs/SM. 3-stage cp.async.
// Stage = A_raw[128][36] + Bh[32][72] + Bl[32][72] = 9216 floats (36KB).
// B pre-split (no B tfsplit in inner loop).
// =====================================================================
#define BMM_STG 9216
__device__ __forceinline__ void bmm_issue_chunk(
    const float* Ag, const float* Bgh, const float* Bgl, uint32_t sbase,
    int kk, int t)
{
    const uint32_t sA = sbase, sBh = sbase + 4608u*4, sBl = sbase + 6912u*4;
    #pragma unroll
    for (int j = 0; j < 4; j++){                 // A: 1024 x 16B granules
        int g = t + j*256, r = g>>3, c4 = (g&7)*4;
        uint32_t dst = sA + (uint32_t)(r*36 + c4)*4;
        const float* src = Ag + (size_t)r*A2 + kk + c4;
        asm volatile("cp.async.cg.shared.global [%0], [%1], 16;" :: "r"(dst), "l"(src));
    }
    #pragma unroll
    for (int j = 0; j < 2; j++){                 // Bh: 512 x 16B granules
        int g = t + j*256, r = g>>4, c4 = (g&15)*4;
        uint32_t dst = sBh + (uint32_t)(r*72 + c4)*4;
        const float* src = Bgh + (size_t)(kk + r)*HH + c4;
        asm volatile("cp.async.cg.shared.global [%0], [%1], 16;" :: "r"(dst), "l"(src));
    }
    #pragma unroll
    for (int j = 0; j < 2; j++){                 // Bl
        int g = t + j*256, r = g>>4, c4 = (g&15)*4;
        uint32_t dst = sBl + (uint32_t)(r*72 + c4)*4;
        const float* src = Bgl + (size_t)(kk + r)*HH + c4;
        asm volatile("cp.async.cg.shared.global [%0], [%1], 16;" :: "r"(dst), "l"(src));
    }
    asm volatile("cp.async.commit_group;" ::: "memory");
}

__global__ void __launch_bounds__(256, 2)
bmm_kernel(const float* __restrict__ Abig){
    extern __shared__ float sm[];
    const int mt = blockIdx.x, y = blockIdx.y;
    const int ks = y & 1, half = (y>>1) & 1, b = y >> 2;
    const int t = threadIdx.x;
    const int kbase = ks * 1024;
    const float* Ag  = Abig + ((size_t)b*NND + mt*128)*A2 + (size_t)half*EN + kbase;
    const float* Bgh = (half ? g_outgh : g_inch) + (size_t)b*EN*HH + (size_t)kbase*HH;
    const float* Bgl = (half ? g_outgl : g_incl) + (size_t)b*EN*HH + (size_t)kbase*HH;
    const size_t outBase = ((size_t)b*NND + mt*128)*HH;
    const uint32_t sbase = smem_u32(sm);

    bmm_issue_chunk(Ag, Bgh, Bgl, sbase, 0, t);
    bmm_issue_chunk(Ag, Bgh, Bgl, sbase + (uint32_t)BMM_STG*4, 32, t);

    const int warp = t>>5, lane = t&31, gid = lane>>2, q = lane&3;
    const int mrow = (warp>>1)*32, ncol = (warp&1)*32;     // 4m x 2n
    float accM[2][4][4] = {}, accC[2][4][4] = {};

    for (int it = 0; it < 32; it++){
        if (it + 2 < 32){
            const int stg = (it+2) % 3;
            bmm_issue_chunk(Ag, Bgh, Bgl, sbase + (uint32_t)(stg*BMM_STG)*4, (it+2)*32, t);
        }
        if (it < 30)       asm volatile("cp.async.wait_group 2;" ::: "memory");
        else if (it == 30) asm volatile("cp.async.wait_group 1;" ::: "memory");
        else               asm volatile("cp.async.wait_group 0;" ::: "memory");
        __syncthreads();
        const float* base = sm + (it % 3)*BMM_STG;
        mma_fragB<36,72,4,4>(base, base + 4608, base + 6912, mrow, ncol, gid, q, accM, accC);
        if ((it & 15) == 15){
            float* P = (half ? g_paout : g_pain)[ks*2 + (it>>4)];
            #pragma unroll
            for (int mi = 0; mi < 2; mi++)
            #pragma unroll
            for (int ni = 0; ni < 4; ni++)
            #pragma unroll
            for (int e2 = 0; e2 < 4; e2++){
                const int fr = mrow + mi*16 + gid + ((e2&2)?8:0);
                const int fc = ncol + ni*8 + q*2 + (e2&1);
                P[outBase + (size_t)fr*HH + fc] = accM[mi][ni][e2] + accC[mi][ni][e2];
                accM[mi][ni][e2] = 0.0f;
                accC[mi][ni][e2] = 0.0f;
            }
        }
        __syncthreads();
    }
}

// =====================================================================
// gate: grid (8mt, B), 256 thr.
// stage 1 = ONE merged GEMM 64x192x192 (concat weights, pre-split, pad0).
// smem: sA[64][196] + sG[64][196] + sWh[32][200] + sWl[32][200] = 148KB
// =====================================================================
__global__ void __launch_bounds__(256)
gate_kernel(const float* __restrict__ tw){
    extern __shared__ float sm[];
    float* sA  = sm;                   // 64*196
    float* sG  = sA + 64*196;          // 64*196
    float* sWh = sG + 64*196;          // 32*200
    float* sWl = sWh + 32*200;         // 32*200
    const int mt = blockIdx.x, b = blockIdx.y, t = threadIdx.x;
    const size_t nodeBase = (size_t)b*NND + (size_t)mt*64;

    // assemble A panel: a_in (sum of 4 partials) | a_out (sum) | hs
    #pragma unroll
    for (int j = 0; j < 4; j++){
        int idx = t + j*256, r = idx>>4, c = (idx&15)*4;
        const size_t off = (nodeBase + r)*HH + c;
        float4 vi = *reinterpret_cast<const float4*>(&g_pain[0][off]);
        float4 vo = *reinterpret_cast<const float4*>(&g_paout[0][off]);
        #pragma unroll
        for (int w = 1; w < 4; w++){
            float4 pi = *reinterpret_cast<const float4*>(&g_pain[w][off]);
            float4 po = *reinterpret_cast<const float4*>(&g_paout[w][off]);
            vi.x += pi.x; vi.y += pi.y; vi.z += pi.z; vi.w += pi.w;
            vo.x += po.x; vo.y += po.y; vo.z += po.z; vo.w += po.w;
        }
        *reinterpret_cast<float4*>(sA + r*196 + c)       = vi;
        *reinterpret_cast<float4*>(sA + r*196 + 64 + c)  = vo;
        *reinterpret_cast<float4*>(sA + r*196 + 128 + c) =
            *reinterpret_cast<const float4*>(g_hs + off);
    }
    __syncthreads();

    const int warp = t>>5, lane = t&31, gid = lane>>2, q = lane&3;

    // ---- stage 1: merged 64x192x192 GEMM. warps 2m x 4n, tile 32x48 (NI=6)
    {
        const int mrow = (warp&1)*32, ncol = (warp>>1)*48;
        float accM[2][6][4] = {}, accC[2][6][4] = {};
        for (int kc = 0; kc < 6; kc++){
            #pragma unroll
            for (int j = 0; j < 6; j++){            // 32x192 = 1536 float4 each
                int idx = t + j*256, r = idx/48, c = (idx%48)*4;
                *reinterpret_cast<float4*>(sWh + r*200 + c) =
                    *reinterpret_cast<const float4*>(g_wch + (size_t)(kc*32+r)*192 + c);
                *reinterpret_cast<float4*>(sWl + r*200 + c) =
                    *reinterpret_cast<const float4*>(g_wcl + (size_t)(kc*32+r)*192 + c);
            }
            __syncthreads();
            mma_fragB<196,200,4,6>(sA + kc*32, sWh, sWl, mrow, ncol, gid, q, accM, accC);
            __syncthreads();
        }
        #pragma unroll
        for (int mi = 0; mi < 2; mi++)
        #pragma unroll
        for (int ni = 0; ni < 6; ni++)
        #pragma unroll
        for (int e2 = 0; e2 < 4; e2++){
            const int fr = mrow + mi*16 + gid + ((e2&2)?8:0);
            const int fc = ncol + ni*8 + q*2 + (e2&1);
            sG[fr*196 + fc] = (accM[mi][ni][e2] + accC[mi][ni][e2]) + __ldg(g_bcat + fc);
        }
    }
    __syncthreads();

    // ---- rh = sigmoid(r_pre) * hs -> sA cols 0..63
    #pragma unroll
    for (int j = 0; j < 16; j++){
        int idx = t + j*256, r = idx>>6, c = idx&63;
        sA[r*196 + c] = sA[r*196 + 128 + c] * sgm(sG[r*196 + 64 + c]);
    }
    __syncthreads();

    // ---- stage 2: h_bot = rh @ tw[128:192]  (warps 4m x 4n16, NI=2)
    const int mrow2 = (warp>>2)*32, ncol2 = (warp&3)*16;
    float acc2M[2][2][4] = {}, acc2C[2][2][4] = {};
    for (int kc = 0; kc < 2; kc++){
        #pragma unroll
        for (int j = 0; j < 2; j++){               // 32x64 = 512 float4
            int idx = t + j*256, r = idx>>4, c = (idx&15)*4;
            *reinterpret_cast<float4*>(sWh + r*72 + c) =
                *reinterpret_cast<const float4*>(tw + (size_t)(128 + kc*32 + r)*64 + c);
        }
        __syncthreads();
        mma_frag<196,72,4,2>(sA + kc*32, sWh, mrow2, ncol2, gid, q, acc2M, acc2C);
        __syncthreads();
    }

    // ---- epilogue
    #pragma unroll
    for (int mi = 0; mi < 2; mi++)
    #pragma unroll
    for (int ni = 0; ni < 2; ni++)
    #pragma unroll
    for (int e2 = 0; e2 < 4; e2++){
        const int fr = mrow2 + mi*16 + gid + ((e2&2)?8:0);
        const int fc = ncol2 + ni*8 + q*2 + (e2&1);
        const size_t node = nodeBase + fr;
        float z  = sgm(sG[fr*196 + fc]);
        float h  = tanhf(sG[fr*196 + 128 + fc] + (acc2M[mi][ni][e2] + acc2C[mi][ni][e2]));
        float hv = sA[fr*196 + 128 + fc];
        g_hs[node*HH + fc] = (1.0f - z)*hv + z*h;
    }
}

// =====================================================================
// att: [hs|annotation] @ {attn_w, st_w} + bias -> g_att (unchanged)
// =====================================================================
__global__ void __launch_bounds__(256)
att_kernel(const float* __restrict__ ann, const float* __restrict__ aw,
           const float* __restrict__ ab, const float* __restrict__ sw,
           const float* __restrict__ sb){
    __shared__ float sA[128*36];
    __shared__ float sB[32*72];
    const int mt = blockIdx.x, b = blockIdx.y, nt = blockIdx.z, t = threadIdx.x;
    const float* W    = nt ? sw : aw;
    const float* bias = nt ? sb : ab;
    const size_t nodeBase = (size_t)b*NND + (size_t)mt*128;
    const int warp = t>>5, lane = t&31, gid = lane>>2, q = lane&3;
    const int mrow = (warp>>1)*32, ncol = (warp&1)*32;
    float accM[2][4][4] = {}, accC[2][4][4] = {};
    for (int kc = 0; kc < 3; kc++){
        const int k0 = kc*32;
        const float* Ag; int rs;
        if (kc < 2){ Ag = g_hs + nodeBase*HH + k0; rs = HH; }
        else       { Ag = ann + nodeBase*AD;       rs = AD; }
        #pragma unroll
        for (int j = 0; j < 4; j++){
            int idx = t + j*256, r = idx>>3, c = (idx&7)*4;
            *reinterpret_cast<float4*>(sA + r*36 + c) =
                *reinterpret_cast<const float4*>(Ag + (size_t)r*rs + c);
        }
        #pragma unroll
        for (int j = 0; j < 2; j++){
            int idx = t + j*256, r = idx>>4, c = (idx&15)*4;
            *reinterpret_cast<float4*>(sB + r*72 + c) =
                *reinterpret_cast<const float4*>(W + (size_t)(k0+r)*64 + c);
        }
        __syncthreads();
        mma_frag<36,72,4,4>(sA, sB, mrow, ncol, gid, q, accM, accC);
        __syncthreads();
    }
    #pragma unroll
    for (int mi = 0; mi < 2; mi++)
    #pragma unroll
    for (int ni = 0; ni < 4; ni++)
    #pragma unroll
    for (int e2 = 0; e2 < 4; e2++){
        const int fr = mrow + mi*16 + gid + ((e2&2)?8:0);
        const int fc = ncol + ni*8 + q*2 + (e2&1);
        g_att[(nodeBase+fr)*128 + nt*64 + fc] =
            (accM[mi][ni][e2] + accC[mi][ni][e2]) + __ldg(bias + fc);
    }
}

// =====================================================================
// reduce: out[b][c] = tanh( sum_n sigmoid(att0)*tanh(att1) ), fp64
// =====================================================================
__global__ void __launch_bounds__(256)
reduce_kernel(float* __restrict__ out){
    __shared__ double red[256];
    const int b = blockIdx.x, t = threadIdx.x;
    const int c = t & 63, seg = t >> 6;
    double acc = 0.0;
    for (int n = seg; n < NND; n += 4){
        const float* p = g_att + ((size_t)b*NND + n)*128;
        double attn = 1.0/(1.0 + exp(-(double)p[c]));
        double ts   = tanh((double)p[64 + c]);
        acc += attn * ts;
    }
    red[t] = acc;
    __syncthreads();
    if (t < 64){
        double s = red[t] + red[t+64] + red[t+128] + red[t+192];
        out[(size_t)b*64 + t] = (float)tanh(s);
    }
}

// =====================================================================
extern "C" void kernel_launch(void* const* d_in, const int* in_sizes, int n_in,
                              void* d_out, int out_size){
    const float* hs   = (const float*)d_in[0];
    const float* ann  = (const float*)d_in[1];
    const float* Abig = (const float*)d_in[2];
    const float* inw  = (const float*)d_in[3];
    const float* inb  = (const float*)d_in[4];
    const float* outw = (const float*)d_in[5];
    const float* outb = (const float*)d_in[6];
    const float* uw   = (const float*)d_in[7];
    const float* ub   = (const float*)d_in[8];
    const float* rw   = (const float*)d_in[9];
    const float* rb   = (const float*)d_in[10];
    const float* tw   = (const float*)d_in[11];
    const float* tb   = (const float*)d_in[12];
    const float* aw   = (const float*)d_in[13];
    const float* ab   = (const float*)d_in[14];
    const float* sw   = (const float*)d_in[15];
    const float* sb   = (const float*)d_in[16];

    const int PROJ_SMEM = (2*128*68 + 2*64*72) * 4;              // 106496 B
    const int BMM_SMEM  = 3 * BMM_STG * 4;                       // 110592 B (2 CTAs/SM)
    const int GATE_SMEM = (2*64*196 + 2*32*200) * 4;             // 151552 B
    cudaFuncSetAttribute(proj_kernel, cudaFuncAttributeMaxDynamicSharedMemorySize, PROJ_SMEM);
    cudaFuncSetAttribute(bmm_kernel,  cudaFuncAttributeMaxDynamicSharedMemorySize, BMM_SMEM);
    cudaFuncSetAttribute(gate_kernel, cudaFuncAttributeMaxDynamicSharedMemorySize, GATE_SMEM);

    cudaMemcpyToSymbolAsync(g_hs, hs, sizeof(float)*BB*NND*HH, 0,
                            cudaMemcpyDeviceToDevice, 0);

    setup_kernel<<<144, 256>>>(uw, rw, tw, ub, rb, tb);
    for (int s = 0; s < STEPS; s++){
        proj_kernel<<<dim3(4, EE, BB), 512, PROJ_SMEM>>>(inw, inb, outw, outb);
        bmm_kernel <<<dim3(4, 64),     256, BMM_SMEM >>>(Abig);
        gate_kernel<<<dim3(8, BB),     256, GATE_SMEM>>>(tw);
    }
    att_kernel<<<dim3(4, BB, 2), 256>>>(ann, aw, ab, sw, sb);
    reduce_kernel<<<BB, 256>>>((float*)d_out);
}